// round 15
// baseline (speedup 1.0000x reference)
#include <cuda_runtime.h>
#include <cstdint>

#define SGRID 14
#define BATCH 4096
#define NCELLS (BATCH * SGRID * SGRID)   // 802816
#define THREADS 128
#define CPB 128                          // cells per block
#define NBLOCKS (NCELLS / CPB)           // 6272
#define TILE_BYTES (CPB * 30 * 4)        // 15360 B per tensor
#define FIX_SCALE 4194304.0f             // 2^22
#define SUM_MASK ((1ull << 48) - 1ull)
#define NBANKS 32

__device__ unsigned long long g_bank[NBANKS];   // zeroed at load; re-zeroed by finalizer

__global__ void __launch_bounds__(THREADS)
yolo_loss_kernel(const float* __restrict__ pred,
                 const float* __restrict__ targ,
                 float* __restrict__ out)
{
    __shared__ alignas(16) float sbuf[2 * CPB * 30];   // pred tile | targ tile (30720 B)
    __shared__ alignas(8) unsigned long long mbar;
    __shared__ float warp_sums[THREADS / 32];

    const size_t base = (size_t)blockIdx.x * (CPB * 30);
    const float* gp = pred + base;
    const float* gt = targ + base;
    const uint32_t sdst  = (uint32_t)__cvta_generic_to_shared(sbuf);
    const uint32_t mbarA = (uint32_t)__cvta_generic_to_shared(&mbar);
    const int tid = threadIdx.x;

    // ---- bulk async stage: 2 x UBLKCP per block, mbarrier completion ----
    if (tid == 0)
        asm volatile("mbarrier.init.shared.b64 [%0], 1;" :: "r"(mbarA) : "memory");
    __syncthreads();
    if (tid == 0) {
        asm volatile("mbarrier.arrive.expect_tx.shared.b64 _, [%0], %1;"
                     :: "r"(mbarA), "r"(2 * TILE_BYTES) : "memory");
        asm volatile("cp.async.bulk.shared::cta.global.mbarrier::complete_tx::bytes "
                     "[%0], [%1], %2, [%3];"
                     :: "r"(sdst), "l"(gp), "r"(TILE_BYTES), "r"(mbarA) : "memory");
        asm volatile("cp.async.bulk.shared::cta.global.mbarrier::complete_tx::bytes "
                     "[%0], [%1], %2, [%3];"
                     :: "r"(sdst + TILE_BYTES), "l"(gt), "r"(TILE_BYTES), "r"(mbarA) : "memory");
    }
    // all threads wait for phase 0 completion (acquire: smem writes visible)
    {
        uint32_t done;
        asm volatile(
            "{\n\t.reg .pred p;\n\t"
            "mbarrier.try_wait.parity.acquire.cta.shared::cta.b64 p, [%1], 0;\n\t"
            "selp.b32 %0, 1, 0, p;\n\t}"
            : "=r"(done) : "r"(mbarA) : "memory");
        if (!done) {
            asm volatile(
                "{\n\t.reg .pred P1;\n\t"
                "WAIT_LOOP:\n\t"
                "mbarrier.try_wait.parity.acquire.cta.shared::cta.b64 P1, [%0], 0, 0x989680;\n\t"
                "@P1 bra.uni WAIT_DONE;\n\t"
                "bra.uni WAIT_LOOP;\n\t"
                "WAIT_DONE:\n\t}"
                :: "r"(mbarA) : "memory");
        }
    }

    const float* p = sbuf + tid * 30;
    const float* t = sbuf + CPB * 30 + tid * 30;

    float loss;
    bool obj = (t[4] > 0.0f);   // target conf is exactly 0.0 or 1.0

    if (obj) {
        // ---- class loss: sum_{c=10..29} (p-t)^2 ----
        float cls = 0.0f;
#pragma unroll
        for (int c = 10; c < 30; c++) {
            float d = p[c] - t[c];
            cls = fmaf(d, d, cls);
        }

        // ---- IoU of both pred boxes vs target box 0 ----
        const float invS = 1.0f / (float)SGRID;
        float tcx = t[0] * invS, tcy = t[1] * invS;
        float t1x = tcx - t[2] * 0.5f, t2x = tcx + t[2] * 0.5f;
        float t1y = tcy - t[3] * 0.5f, t2y = tcy + t[3] * 0.5f;
        float area_t = (t2x - t1x) * (t2y - t1y);

        float iou0, iou1;
#pragma unroll
        for (int b = 0; b < 2; b++) {
            float bx = (b == 0) ? p[0] : p[5];
            float by = (b == 0) ? p[1] : p[6];
            float bw = (b == 0) ? p[2] : p[7];
            float bh = (b == 0) ? p[3] : p[8];
            float cx = bx * invS, cy = by * invS;
            float p1x = cx - bw * 0.5f, p2x = cx + bw * 0.5f;
            float p1y = cy - bh * 0.5f, p2y = cy + bh * 0.5f;
            float ltx = fmaxf(p1x, t1x), lty = fmaxf(p1y, t1y);
            float rbx = fminf(p2x, t2x), rby = fminf(p2y, t2y);
            float wx = fmaxf(rbx - ltx, 0.0f);
            float wy = fmaxf(rby - lty, 0.0f);
            float inter = wx * wy;
            float area_p = (p2x - p1x) * (p2y - p1y);
            float iou = inter / (area_p + area_t - inter);
            if (b == 0) iou0 = iou; else iou1 = iou;
        }

        bool pick1 = (iou0 <= iou1);
        float iou_best = pick1 ? iou1 : iou0;

        float psx = pick1 ? p[5] : p[0];
        float psy = pick1 ? p[6] : p[1];
        float psw = pick1 ? p[7] : p[2];
        float psh = pick1 ? p[8] : p[3];
        float psc = pick1 ? p[9] : p[4];
        float tsx = pick1 ? t[5] : t[0];
        float tsy = pick1 ? t[6] : t[1];
        float tsw = pick1 ? t[7] : t[2];
        float tsh = pick1 ? t[8] : t[3];

        float dx = psx - tsx, dy = psy - tsy;
        float dw = sqrtf(psw) - sqrtf(tsw);
        float dh = sqrtf(psh) - sqrtf(tsh);
        float reg = dx*dx + dy*dy + dw*dw + dh*dh;

        float dc = psc - iou_best;

        loss = cls + 5.0f * reg + dc * dc;
    } else {
        // ---- no-object loss on both confidences ----
        float d4 = p[4] - t[4];
        float d9 = p[9] - t[9];
        loss = 0.5f * (d4 * d4 + d9 * d9);
    }

    // ---- reduction: warp shfl -> smem -> ONE returnless banked u64 RED ----
#pragma unroll
    for (int o = 16; o > 0; o >>= 1)
        loss += __shfl_xor_sync(0xffffffffu, loss, o);

    int wid = tid >> 5;
    int lid = tid & 31;
    if (lid == 0) warp_sums[wid] = loss;
    __syncthreads();

    if (tid == 0) {
        float bsum = warp_sums[0] + warp_sums[1] + warp_sums[2] + warp_sums[3];
        unsigned long long pack = (1ull << 48) |
            (unsigned long long)__float2ull_rn(bsum * FIX_SCALE);   // bsum >= 0
        unsigned long long* bank = &g_bank[blockIdx.x & (NBANKS - 1)];
        // fire-and-forget: block retires without waiting on the L2 round-trip
        asm volatile("red.relaxed.gpu.global.add.u64 [%0], %1;"
                     :: "l"(bank), "l"(pack) : "memory");
    }

    // ---- finalizer: one warp of the LAST-launched block polls the banks ----
    if (blockIdx.x == NBLOCKS - 1 && tid < 32) {
        unsigned long long v;
        unsigned int ctot;
#pragma unroll 1
        do {
            asm volatile("ld.relaxed.gpu.global.u64 %0, [%1];"
                         : "=l"(v) : "l"(&g_bank[tid]));
            ctot = (unsigned int)(v >> 48);
#pragma unroll
            for (int o = 16; o > 0; o >>= 1)
                ctot += __shfl_xor_sync(0xffffffffu, ctot, o);
        } while (ctot != (unsigned int)NBLOCKS);

        // counts full => the v's we hold contain the complete sums
        unsigned long long s = v & SUM_MASK;
#pragma unroll
        for (int o = 16; o > 0; o >>= 1)
            s += __shfl_xor_sync(0xffffffffu, s, o);

        if (tid == 0)
            out[0] = (float)((double)s * (1.0 / (double)FIX_SCALE)
                             * (1.0 / (double)BATCH));
        // self-clean for the next graph replay (no REDs remain in flight)
        g_bank[tid] = 0ull;
    }
}

extern "C" void kernel_launch(void* const* d_in, const int* in_sizes, int n_in,
                              void* d_out, int out_size)
{
    const float* pred = (const float*)d_in[0];
    const float* targ = (const float*)d_in[1];
    float* out = (float*)d_out;
    (void)in_sizes; (void)n_in; (void)out_size;

    yolo_loss_kernel<<<NBLOCKS, THREADS>>>(pred, targ, out);
}